// round 9
// baseline (speedup 1.0000x reference)
#include <cuda_runtime.h>
#include <cuda_bf16.h>
#include <cstdint>

// MySoftBCELoss: B=1048576 rows, C=32 classes, fp32 -> scalar.
// Warp-autonomous persistent pipelines, 3-deep cp.async buffering.
// 8-row warp tiles, 4 lanes/row (8 classes each); MUFU softplus.

#define BLOCK 128
#define WARPS (BLOCK / 32)                  // 4
#define TILE_ROWS 8
#define NBUF 3
#define NCLS 32
#define ROWS_TOTAL 1048576
#define NTILES (ROWS_TOTAL / TILE_ROWS)     // 131072
#define NCTAS (148 * 8)                     // 1184
#define TOTAL_WARPS (NCTAS * WARPS)         // 4736
#define PITCH4 9                            // float4 per smem row (144 B)
#define T4_PER_TILE (TILE_ROWS * NCLS / 4)  // 64 float4 per tensor per tile
#define WBUF4 (TILE_ROWS * PITCH4)          // 72 float4 per tensor per buf
#define LOG_EPS (-16.11809565095832f)       // log(1e-7)

__device__ float g_partials[NCTAS];
__device__ int   g_count = 0;

__device__ __forceinline__ void cp_async16(unsigned int saddr, const void* gptr) {
    asm volatile("cp.async.cg.shared.global [%0], [%1], 16;\n"
                 :: "r"(saddr), "l"(gptr));
}
__device__ __forceinline__ void cp_commit() { asm volatile("cp.async.commit_group;\n"); }
__device__ __forceinline__ void cp_wait2()  { asm volatile("cp.async.wait_group 2;\n" ::: "memory"); }

__global__ void __launch_bounds__(BLOCK, 8) softbce_warp3(
    const float4* __restrict__ logits4,
    const float4* __restrict__ target4,
    float* __restrict__ out)
{
    // [warp][buf][tensor][row * PITCH4 + q]
    __shared__ float4 sbuf[WARPS][NBUF][2][WBUF4];   // 4*3*2*72*16 = 27648 B
    __shared__ float  warp_sums[WARPS];
    __shared__ bool   is_last;

    const int tid     = threadIdx.x;
    const int wid     = tid >> 5;
    const int lane    = tid & 31;
    const int row     = lane >> 2;       // 0..7
    const int quarter = lane & 3;        // 4 lanes per row, 8 classes each
    const unsigned m  = 0xFFFFFFFFu;

    const int gwarp   = blockIdx.x * WARPS + wid;            // 0..4735
    const int n_tiles = (NTILES - 1 - gwarp) / TOTAL_WARPS + 1;  // >= 27

    const unsigned int wbase =
        (unsigned int)__cvta_generic_to_shared(&sbuf[wid][0][0][0]);
    const unsigned int bufStride  = (unsigned int)(2 * WBUF4 * 16);
    const unsigned int tensStride = (unsigned int)(WBUF4 * 16);

    // staging offsets: fi in {lane, lane+32}; srow = fi>>3, sq = fi&7
    unsigned int soff[2];
    #pragma unroll
    for (int it = 0; it < 2; it++) {
        int fi   = lane + it * 32;
        soff[it] = (unsigned int)(((fi >> 3) * PITCH4 + (fi & 7)) * 16);
    }

    // per-lane global pointers, advanced by a constant stride each staged tile
    const size_t stride4 = (size_t)TOTAL_WARPS * T4_PER_TILE;
    const float4* pL0 = logits4 + (size_t)gwarp * T4_PER_TILE + lane;
    const float4* pL1 = pL0 + 32;
    const float4* pT0 = target4 + (size_t)gwarp * T4_PER_TILE + lane;
    const float4* pT1 = pT0 + 32;

    float acc = 0.0f;

    // ---- prologue: stage this warp's first NBUF tiles ----
    #pragma unroll
    for (int s = 0; s < NBUF; s++) {
        const unsigned int bb = wbase + (unsigned int)s * bufStride;
        cp_async16(bb + soff[0],              pL0);
        cp_async16(bb + soff[1],              pL1);
        cp_async16(bb + tensStride + soff[0], pT0);
        cp_async16(bb + tensStride + soff[1], pT1);
        cp_commit();
        pL0 += stride4; pL1 += stride4; pT0 += stride4; pT1 += stride4;
    }

    int buf = 0;
    for (int k = 0; k < n_tiles; k++) {
        cp_wait2();              // oldest group (tile k) complete
        __syncwarp(m);

        // ---- compute: 4 lanes per row, 8 classes each ----
        const float4* lrow = &sbuf[wid][buf][0][row * PITCH4 + quarter * 2];
        const float4* trow = &sbuf[wid][buf][1][row * PITCH4 + quarter * 2];

        float psum  = 0.0f;
        float tmax  = -1.0f;
        int   cmax  = NCLS;
        float lpmax = 0.0f;
        float l1p0  = 0.0f;      // valid on quarter==0

        #pragma unroll
        for (int q = 0; q < 2; q++) {
            float4 lv = lrow[q];
            float4 tv = trow[q];
            float xs[4] = {lv.x, lv.y, lv.z, lv.w};
            float ts[4] = {tv.x, tv.y, tv.z, tv.w};
            #pragma unroll
            for (int kk = 0; kk < 4; kk++) {
                float x = xs[kk];
                float t = ts[kk];
                float u = fabsf(x);
                float e  = __expf(-u);             // MUFU.EX2 path
                float s0 = __logf(1.0f + e);       // MUFU.LG2 path
                float L  = fmaxf(x, 0.0f) + s0;    // softplus(x)
                float lp  = fmaxf(x - L, LOG_EPS);
                float l1p = fmaxf(-L,    LOG_EPS);
                psum += fmaf(t, lp - l1p, l1p);    // t*lp + (1-t)*l1p
                int c = quarter * 8 + q * 4 + kk;
                if (c == 0) l1p0 = l1p;
                if (t > tmax) { tmax = t; cmax = c; lpmax = lp; }
            }
        }

        // ---- width-4 combine across the row's four lanes ----
        psum += __shfl_xor_sync(m, psum, 1, 4);
        psum += __shfl_xor_sync(m, psum, 2, 4);
        #pragma unroll
        for (int o = 2; o > 0; o >>= 1) {
            float ot  = __shfl_xor_sync(m, tmax,  o, 4);
            int   oc  = __shfl_xor_sync(m, cmax,  o, 4);
            float olp = __shfl_xor_sync(m, lpmax, o, 4);
            if (ot > tmax || (ot == tmax && oc < cmax)) {
                tmax = ot; cmax = oc; lpmax = olp;
            }
        }
        l1p0 = __shfl_sync(m, l1p0, 0, 4);   // from quarter==0 lane

        if (quarter == 0) {
            acc += (cmax == 0) ? (psum * (1.0f / (float)NCLS))
                               : fmaf(tmax, lpmax, l1p0);
        }

        __syncwarp(m);           // all lanes done reading buf

        // ---- stage tile k+NBUF into this (now free) buffer ----
        if (k + NBUF < n_tiles) {
            const unsigned int bb = wbase + (unsigned int)buf * bufStride;
            cp_async16(bb + soff[0],              pL0);
            cp_async16(bb + soff[1],              pL1);
            cp_async16(bb + tensStride + soff[0], pT0);
            cp_async16(bb + tensStride + soff[1], pT1);
            pL0 += stride4; pL1 += stride4; pT0 += stride4; pT1 += stride4;
        }
        cp_commit();             // possibly-empty group keeps ring aligned

        buf = (buf == NBUF - 1) ? 0 : buf + 1;
    }

    // ---- warp reduce (only quarter==0 lanes hold data) ----
    #pragma unroll
    for (int o = 16; o > 0; o >>= 1)
        acc += __shfl_xor_sync(m, acc, o);
    if (lane == 0) warp_sums[wid] = acc;
    __syncthreads();

    if (tid == 0) {
        g_partials[blockIdx.x] = warp_sums[0] + warp_sums[1]
                               + warp_sums[2] + warp_sums[3];
        __threadfence();
        int prev = atomicAdd(&g_count, 1);
        is_last = (prev == NCTAS - 1);
    }
    __syncthreads();

    // ---- last CTA: deterministic final reduce ----
    if (is_last) {
        float s = 0.0f;
        for (int i = tid; i < NCTAS; i += BLOCK)
            s += g_partials[i];
        #pragma unroll
        for (int o = 16; o > 0; o >>= 1)
            s += __shfl_xor_sync(m, s, o);
        if ((tid & 31) == 0) warp_sums[tid >> 5] = s;
        __syncthreads();
        if (tid == 0) {
            out[0] = -(warp_sums[0] + warp_sums[1] + warp_sums[2] + warp_sums[3])
                     * (1.0f / (float)ROWS_TOTAL);
            g_count = 0;   // reset for next graph replay
        }
    }
}

extern "C" void kernel_launch(void* const* d_in, const int* in_sizes, int n_in,
                              void* d_out, int out_size)
{
    const float4* logits = (const float4*)d_in[0];
    const float4* target = (const float4*)d_in[1];
    float* out = (float*)d_out;

    softbce_warp3<<<NCTAS, BLOCK>>>(logits, target, out);
}

// round 10
// speedup vs baseline: 1.0396x; 1.0396x over previous
#include <cuda_runtime.h>
#include <cuda_bf16.h>
#include <cstdint>

// MySoftBCELoss: B=1048576 rows, C=32 classes, fp32 -> scalar.
// Traffic-reduced algorithm:
//   - stream target fully (argmax + t_lab), warp-autonomous cp.async pipeline
//   - rows with label!=0: gather logits[row,label], logits[row,0] only
//   - rows with label==0 (~3%): predicated full-row BCE
// softplus via MUFU: L = max(x,0)+log1p(exp(-|x|)); lp=x-L, l1p=-L (clamped).

#define BLOCK 128
#define WARPS (BLOCK / 32)                   // 4
#define TILE_ROWS 32                         // rows per warp-tile (1 lane/row)
#define NCLS 32
#define ROWS_TOTAL 1048576
#define NTILES (ROWS_TOTAL / TILE_ROWS)      // 32768
#define NCTAS (148 * 6)                      // 888 persistent CTAs
#define TOTAL_WARPS (NCTAS * WARPS)          // 3552
#define PITCH4 9                             // float4 per smem row (144 B)
#define T4_PER_TILE (TILE_ROWS * NCLS / 4)   // 256 float4 per tile (target only)
#define WBUF4 (TILE_ROWS * PITCH4)           // 288 float4 per buf

#define LOG_EPS   (-16.11809565095832f)      // log(1e-7)
#define LOG_1MEPS (-1.0000000494736474e-07f) // log(1 - 1e-7)

__device__ float g_partials[NCTAS];
__device__ int   g_count = 0;

__device__ __forceinline__ void cp_async16(unsigned int saddr, const void* gptr) {
    asm volatile("cp.async.cg.shared.global [%0], [%1], 16;\n"
                 :: "r"(saddr), "l"(gptr));
}
__device__ __forceinline__ void cp_commit() { asm volatile("cp.async.commit_group;\n"); }
__device__ __forceinline__ void cp_wait1()  { asm volatile("cp.async.wait_group 1;\n" ::: "memory"); }
__device__ __forceinline__ void cp_wait0()  { asm volatile("cp.async.wait_group 0;\n" ::: "memory"); }

__device__ __forceinline__ float softplus_f(float x) {
    return fmaxf(x, 0.0f) + __logf(1.0f + __expf(-fabsf(x)));
}
__device__ __forceinline__ float clamp_log(float v) {
    return fminf(fmaxf(v, LOG_EPS), LOG_1MEPS);
}

__global__ void __launch_bounds__(BLOCK) softbce_gather(
    const float*  __restrict__ logits,
    const float4* __restrict__ target4,
    float* __restrict__ out)
{
    // [warp][buf][row * PITCH4 + q]  (target only)
    __shared__ float4 sbuf[WARPS][2][WBUF4];   // 4*2*288*16 = 36864 B
    __shared__ float  warp_sums[WARPS];
    __shared__ bool   is_last;

    const int tid  = threadIdx.x;
    const int wid  = tid >> 5;
    const int lane = tid & 31;
    const unsigned m = 0xFFFFFFFFu;

    const int gwarp = blockIdx.x * WARPS + wid;     // 0..3551

    const unsigned int wbase =
        (unsigned int)__cvta_generic_to_shared(&sbuf[wid][0][0]);
    const unsigned int bufStride = (unsigned int)(WBUF4 * 16);

    // staging offsets: fi = lane + it*32 (0..255); srow = fi>>3, q = fi&7
    unsigned int soff[8];
    #pragma unroll
    for (int it = 0; it < 8; it++) {
        int fi   = lane + it * 32;
        soff[it] = (unsigned int)(((fi >> 3) * PITCH4 + (fi & 7)) * 16);
    }

    float acc = 0.0f;

    // ---- prologue: stage target tile gwarp into buf 0 ----
    {
        const size_t gbase = (size_t)gwarp * T4_PER_TILE;
        #pragma unroll
        for (int it = 0; it < 8; it++)
            cp_async16(wbase + soff[it], target4 + gbase + lane + it * 32);
        cp_commit();
    }

    int buf = 0;
    for (int tile = gwarp; tile < NTILES; tile += TOTAL_WARPS) {
        int next = tile + TOTAL_WARPS;
        if (next < NTILES) {
            const size_t gbase = (size_t)next * T4_PER_TILE;
            const unsigned int bb = wbase + (unsigned int)(buf ^ 1) * bufStride;
            #pragma unroll
            for (int it = 0; it < 8; it++)
                cp_async16(bb + soff[it], target4 + gbase + lane + it * 32);
            cp_commit();
            cp_wait1();
        } else {
            cp_wait0();
        }
        __syncwarp(m);

        // ---- my row: scan target for argmax (first occurrence) ----
        const float4* trow = &sbuf[wid][buf][lane * PITCH4];
        float tmax = -1.0f;
        int   cmax = 0;
        #pragma unroll
        for (int q = 0; q < 8; q++) {
            float4 tv = trow[q];
            float ts[4] = {tv.x, tv.y, tv.z, tv.w};
            #pragma unroll
            for (int k = 0; k < 4; k++) {
                int c = q * 4 + k;
                if (ts[k] > tmax) { tmax = ts[k]; cmax = c; }
            }
        }

        const size_t row_g = (size_t)tile * TILE_ROWS + lane;
        const float* lrowg = logits + row_g * NCLS;

        float loss;
        if (cmax != 0) {
            // gather 2 scalars; 2 softplus
            float xlab = __ldg(lrowg + cmax);
            float x0   = __ldg(lrowg);
            float lp_lab = clamp_log(xlab - softplus_f(xlab));
            float l1p0   = clamp_log(-softplus_f(x0));
            loss = fmaf(tmax, lp_lab, l1p0);    // NEG_WEIGHT = 1
        } else {
            // rare heavy path: full-row soft BCE mean
            const float4* lrow4 = (const float4*)lrowg;
            float sum0 = 0.0f;
            #pragma unroll
            for (int q = 0; q < 8; q++) {
                float4 lv = __ldg(lrow4 + q);
                float4 tv = trow[q];
                float xs[4] = {lv.x, lv.y, lv.z, lv.w};
                float ts[4] = {tv.x, tv.y, tv.z, tv.w};
                #pragma unroll
                for (int k = 0; k < 4; k++) {
                    float L   = softplus_f(xs[k]);
                    float lp  = clamp_log(xs[k] - L);
                    float l1p = clamp_log(-L);
                    sum0 += fmaf(ts[k], lp - l1p, l1p);
                }
            }
            loss = sum0 * (1.0f / (float)NCLS);
        }
        acc += loss;

        __syncwarp(m);      // all lanes done with buf before next restage
        buf ^= 1;
    }

    // ---- warp reduce ----
    #pragma unroll
    for (int o = 16; o > 0; o >>= 1)
        acc += __shfl_xor_sync(m, acc, o);
    if (lane == 0) warp_sums[wid] = acc;
    __syncthreads();

    if (tid == 0) {
        g_partials[blockIdx.x] = warp_sums[0] + warp_sums[1]
                               + warp_sums[2] + warp_sums[3];
        __threadfence();
        int prev = atomicAdd(&g_count, 1);
        is_last = (prev == NCTAS - 1);
    }
    __syncthreads();

    // ---- last CTA: deterministic final reduce ----
    if (is_last) {
        float s = 0.0f;
        for (int i = tid; i < NCTAS; i += BLOCK)
            s += g_partials[i];
        #pragma unroll
        for (int o = 16; o > 0; o >>= 1)
            s += __shfl_xor_sync(m, s, o);
        if ((tid & 31) == 0) warp_sums[tid >> 5] = s;
        __syncthreads();
        if (tid == 0) {
            out[0] = -(warp_sums[0] + warp_sums[1] + warp_sums[2] + warp_sums[3])
                     * (1.0f / (float)ROWS_TOTAL);
            g_count = 0;   // reset for next graph replay
        }
    }
}

extern "C" void kernel_launch(void* const* d_in, const int* in_sizes, int n_in,
                              void* d_out, int out_size)
{
    const float*  logits = (const float*)d_in[0];
    const float4* target = (const float4*)d_in[1];
    float* out = (float*)d_out;

    softbce_gather<<<NCTAS, BLOCK>>>(logits, target, out);
}